// round 2
// baseline (speedup 1.0000x reference)
#include <cuda_runtime.h>

#define NN 100000
#define EE 3200000
#define DD 16
#define ATTN_SLOPE 0.2f
#define ACT_SLOPE 0.01f
#define SCAN_BLK 1024
#define NSCAN ((NN + SCAN_BLK - 1) / SCAN_BLK)   // 98

// Scratch (device globals: allocation-free rule)
__device__ float g_featS[NN * DD];
__device__ float g_featD[NN * DD];
__device__ float g_h2[NN * DD];
__device__ int   g_count[NN];
__device__ int   g_offset[NN];
__device__ int   g_cursor[NN];
__device__ int   g_ssrc[EE];
__device__ int   g_bsum[128];

// ---------------------------------------------------------------------------
// Kernel 1: node transforms. 4 threads per node; thread q computes output
// columns [4q, 4q+4) of both feat_src and feat_dst. Also zeroes g_count.
// h == nullptr -> read g_h2 (layer 2 input).
// ---------------------------------------------------------------------------
__global__ void __launch_bounds__(256) node_transform4(
    const float* __restrict__ h,
    const float* __restrict__ Wsrc, const float* __restrict__ bsrc,
    const float* __restrict__ Wdst, const float* __restrict__ bdst,
    int n_nodes)
{
    __shared__ float sWs[DD * DD];
    __shared__ float sWd[DD * DD];
    __shared__ float sbs[DD];
    __shared__ float sbd[DD];

    int tid = threadIdx.x;
    if (tid < DD * DD) { sWs[tid] = Wsrc[tid]; sWd[tid] = Wdst[tid]; }
    if (tid < DD)      { sbs[tid] = bsrc[tid]; sbd[tid] = bdst[tid]; }
    __syncthreads();

    int g = blockIdx.x * 256 + tid;
    int n = g >> 2;
    int q = g & 3;
    if (n >= n_nodes) return;

    const float* hrow = (h != nullptr) ? (h + (size_t)n * DD) : (g_h2 + (size_t)n * DD);
    const float4* hp = reinterpret_cast<const float4*>(hrow);
    float4 t0 = hp[0], t1 = hp[1], t2 = hp[2], t3 = hp[3];
    float hv[DD];
    hv[0]=t0.x;  hv[1]=t0.y;  hv[2]=t0.z;  hv[3]=t0.w;
    hv[4]=t1.x;  hv[5]=t1.y;  hv[6]=t1.z;  hv[7]=t1.w;
    hv[8]=t2.x;  hv[9]=t2.y;  hv[10]=t2.z; hv[11]=t2.w;
    hv[12]=t3.x; hv[13]=t3.y; hv[14]=t3.z; hv[15]=t3.w;

    int c0 = q * 4;
    float fs[4], fd[4];
#pragma unroll
    for (int j = 0; j < 4; j++) { fs[j] = sbs[c0 + j]; fd[j] = sbd[c0 + j]; }
#pragma unroll
    for (int i = 0; i < DD; i++) {
        float hi = hv[i];
#pragma unroll
        for (int j = 0; j < 4; j++) {
            fs[j] = fmaf(hi, sWs[i * DD + c0 + j], fs[j]);
            fd[j] = fmaf(hi, sWd[i * DD + c0 + j], fd[j]);
        }
    }

    reinterpret_cast<float4*>(g_featS + (size_t)n * DD)[q] =
        make_float4(fs[0], fs[1], fs[2], fs[3]);
    reinterpret_cast<float4*>(g_featD + (size_t)n * DD)[q] =
        make_float4(fd[0], fd[1], fd[2], fd[3]);
    if (q == 0) g_count[n] = 0;
}

// ---------------------------------------------------------------------------
// Kernel 2: histogram of dst
// ---------------------------------------------------------------------------
__global__ void __launch_bounds__(256) histogram_k(const int* __restrict__ dst, int n_edges)
{
    int e = blockIdx.x * blockDim.x + threadIdx.x;
    if (e < n_edges) atomicAdd(&g_count[dst[e]], 1);
}

// ---------------------------------------------------------------------------
// Kernels 3a/3b/3c: exclusive scan of g_count -> g_offset (3-kernel scan)
// ---------------------------------------------------------------------------
__global__ void __launch_bounds__(256) scan1(int n)
{
    __shared__ int s[256];
    int b = blockIdx.x, t = threadIdx.x;
    int base = b * SCAN_BLK + t * 4;
    int v[4];
#pragma unroll
    for (int i = 0; i < 4; i++) v[i] = (base + i < n) ? g_count[base + i] : 0;
    int sum = v[0] + v[1] + v[2] + v[3];
    s[t] = sum;
    __syncthreads();
    for (int d = 1; d < 256; d <<= 1) {
        int x = (t >= d) ? s[t - d] : 0;
        __syncthreads();
        s[t] += x;
        __syncthreads();
    }
    int excl = s[t] - sum;            // exclusive prefix over thread sums
    if (t == 255) g_bsum[b] = s[255]; // block total
    int run = excl;
#pragma unroll
    for (int i = 0; i < 4; i++) {
        if (base + i < n) g_offset[base + i] = run;
        run += v[i];
    }
}

__global__ void scan2(int nb)  // 1 block, 128 threads
{
    __shared__ int s[128];
    int t = threadIdx.x;
    int orig = (t < nb) ? g_bsum[t] : 0;
    s[t] = orig;
    __syncthreads();
    for (int d = 1; d < 128; d <<= 1) {
        int x = (t >= d) ? s[t - d] : 0;
        __syncthreads();
        s[t] += x;
        __syncthreads();
    }
    if (t < nb) g_bsum[t] = s[t] - orig;  // exclusive block prefix
}

__global__ void __launch_bounds__(256) scan3(int n)
{
    int i = blockIdx.x * blockDim.x + threadIdx.x;
    if (i < n) {
        int o = g_offset[i] + g_bsum[i >> 10];
        g_offset[i] = o;
        g_cursor[i] = o;
    }
}

// ---------------------------------------------------------------------------
// Kernel 4: scatter src indices into dst-sorted order
// ---------------------------------------------------------------------------
__global__ void __launch_bounds__(256) scatter_k(const int* __restrict__ src,
                                                 const int* __restrict__ dst,
                                                 int n_edges)
{
    int e = blockIdx.x * blockDim.x + threadIdx.x;
    if (e >= n_edges) return;
    int t = dst[e];
    int p = atomicAdd(&g_cursor[t], 1);
    g_ssrc[p] = src[e];
}

// ---------------------------------------------------------------------------
// Kernel 5: warp-per-node aggregation. featD[node] loaded once; gather
// featS[src] per edge; register accumulation; warp butterfly reduce;
// fused normalize + leaky_relu + store. No fp atomics.
// ---------------------------------------------------------------------------
__global__ void __launch_bounds__(256) aggregate_k(const float* __restrict__ attn,
                                                   float* __restrict__ outp,
                                                   int n_nodes)
{
    __shared__ float sa[DD];
    if (threadIdx.x < DD) sa[threadIdx.x] = attn[threadIdx.x];
    __syncthreads();

    int gw = (blockIdx.x * 256 + threadIdx.x) >> 5;
    int lane = threadIdx.x & 31;
    if (gw >= n_nodes) return;

    int beg = g_offset[gw];
    int deg = g_count[gw];

    const float4* fdp = reinterpret_cast<const float4*>(g_featD + (size_t)gw * DD);
    float4 d0 = fdp[0], d1 = fdp[1], d2 = fdp[2], d3 = fdp[3];
    float fd[DD];
    fd[0]=d0.x;  fd[1]=d0.y;  fd[2]=d0.z;  fd[3]=d0.w;
    fd[4]=d1.x;  fd[5]=d1.y;  fd[6]=d1.z;  fd[7]=d1.w;
    fd[8]=d2.x;  fd[9]=d2.y;  fd[10]=d2.z; fd[11]=d2.w;
    fd[12]=d3.x; fd[13]=d3.y; fd[14]=d3.z; fd[15]=d3.w;

    float acc[DD];
#pragma unroll
    for (int k = 0; k < DD; k++) acc[k] = 0.f;
    float den = 0.f;

    for (int base = 0; base < deg; base += 32) {
        int i = base + lane;
        if (i < deg) {
            int s = g_ssrc[beg + i];
            const float4* fsp = reinterpret_cast<const float4*>(g_featS + (size_t)s * DD);
            float4 a0 = fsp[0], a1 = fsp[1], a2 = fsp[2], a3 = fsp[3];
            float fa[DD];
            fa[0]=a0.x;  fa[1]=a0.y;  fa[2]=a0.z;  fa[3]=a0.w;
            fa[4]=a1.x;  fa[5]=a1.y;  fa[6]=a1.z;  fa[7]=a1.w;
            fa[8]=a2.x;  fa[9]=a2.y;  fa[10]=a2.z; fa[11]=a2.w;
            fa[12]=a3.x; fa[13]=a3.y; fa[14]=a3.z; fa[15]=a3.w;

            float sc = 0.f;
#pragma unroll
            for (int k = 0; k < DD; k++) {
                float x = fa[k] + fd[k];
                x = (x > 0.f) ? x : ATTN_SLOPE * x;
                sc = fmaf(sa[k], x, sc);
            }
            float ex = __expf(sc);
            den += ex;
#pragma unroll
            for (int k = 0; k < DD; k++) acc[k] = fmaf(ex, fa[k], acc[k]);
        }
    }

    // warp butterfly reduce (17 values)
#pragma unroll
    for (int o = 16; o > 0; o >>= 1) {
        den += __shfl_xor_sync(0xffffffffu, den, o);
#pragma unroll
        for (int k = 0; k < DD; k++) acc[k] += __shfl_xor_sync(0xffffffffu, acc[k], o);
    }

    if (lane == 0) {
        float inv = (den > 0.f) ? (1.0f / den) : 0.0f;
        float4* op = reinterpret_cast<float4*>(outp + (size_t)gw * DD);
#pragma unroll
        for (int q = 0; q < 4; q++) {
            float r0 = acc[4*q + 0] * inv;
            float r1 = acc[4*q + 1] * inv;
            float r2 = acc[4*q + 2] * inv;
            float r3 = acc[4*q + 3] * inv;
            r0 = (r0 > 0.f) ? r0 : ACT_SLOPE * r0;
            r1 = (r1 > 0.f) ? r1 : ACT_SLOPE * r1;
            r2 = (r2 > 0.f) ? r2 : ACT_SLOPE * r2;
            r3 = (r3 > 0.f) ? r3 : ACT_SLOPE * r3;
            op[q] = make_float4(r0, r1, r2, r3);
        }
    }
}

// ---------------------------------------------------------------------------
static void run_layer(const float* h, const int* src, const int* dst,
                      const float* Wsrc, const float* bsrc,
                      const float* Wdst, const float* bdst,
                      const float* attn, float* outp,
                      int n_nodes, int n_edges)
{
    int nblk4 = (n_nodes * 4 + 255) / 256;
    int nblk  = (n_nodes + 255) / 256;
    int eblk  = (n_edges + 255) / 256;
    int wblk  = (n_nodes * 32 + 255) / 256;

    node_transform4<<<nblk4, 256>>>(h, Wsrc, bsrc, Wdst, bdst, n_nodes);
    histogram_k<<<eblk, 256>>>(dst, n_edges);
    scan1<<<NSCAN, 256>>>(n_nodes);
    scan2<<<1, 128>>>(NSCAN);
    scan3<<<nblk, 256>>>(n_nodes);
    scatter_k<<<eblk, 256>>>(src, dst, n_edges);
    aggregate_k<<<wblk, 256>>>(attn, outp, n_nodes);
}

extern "C" void kernel_launch(void* const* d_in, const int* in_sizes, int n_in,
                              void* d_out, int out_size)
{
    const float* emb   = (const float*)d_in[0];
    const int*   src1  = (const int*)d_in[1];
    const int*   dst1  = (const int*)d_in[2];
    const int*   src2  = (const int*)d_in[3];
    const int*   dst2  = (const int*)d_in[4];
    const float* Wsrc1 = (const float*)d_in[5];
    const float* bsrc1 = (const float*)d_in[6];
    const float* Wdst1 = (const float*)d_in[7];
    const float* bdst1 = (const float*)d_in[8];
    const float* attn1 = (const float*)d_in[9];
    const float* Wsrc2 = (const float*)d_in[10];
    const float* bsrc2 = (const float*)d_in[11];
    const float* Wdst2 = (const float*)d_in[12];
    const float* bdst2 = (const float*)d_in[13];
    const float* attn2 = (const float*)d_in[14];

    int n_nodes  = in_sizes[0] / DD;
    int n_edges1 = in_sizes[1];
    int n_edges2 = in_sizes[3];
    float* out = (float*)d_out;

    // h2 pointer via device symbol is not queryable without API calls here;
    // aggregate of layer 1 writes g_h2 through a kernel-visible pointer:
    // we pass nullptr to mean "g_h2" inside kernels that need it.
    // For aggregate we need an actual pointer; use a small trampoline:
    // layer 1 writes to g_h2 via a device-global alias set by a kernel-arg trick.
    // Simpler: aggregate_k takes outp; we need g_h2's address. Use
    // cudaGetSymbolAddress is allowed (no alloc) but must be done per call;
    // it is not a sync/alloc API, so it is graph-capture safe (host-side only,
    // called before capture region kernels are enqueued).
    static float* h2_ptr = nullptr;
    if (h2_ptr == nullptr) {
        void* p = nullptr;
        cudaGetSymbolAddress(&p, g_h2);
        h2_ptr = (float*)p;
    }

    // Layer 1: emb -> g_h2
    run_layer(emb, src1, dst1, Wsrc1, bsrc1, Wdst1, bdst1, attn1, h2_ptr,
              n_nodes, n_edges1);
    // Layer 2: g_h2 -> out
    run_layer(nullptr, src2, dst2, Wsrc2, bsrc2, Wdst2, bdst2, attn2, out,
              n_nodes, n_edges2);
}

// round 3
// speedup vs baseline: 1.1676x; 1.1676x over previous
#include <cuda_runtime.h>
#include <cstdint>

#define NN 100000
#define EE 3200000
#define DD 16
#define ACT_SLOPE 0.01f

// Scratch (device globals: allocation-free rule)
__device__ float g_featS[NN * DD];
__device__ float g_featD[NN * DD];
__device__ float g_accum[NN * DD];
__device__ float g_denom[NN];
__device__ float g_h2[NN * DD];

// ---- packed f32x2 helpers (sm_103a) ---------------------------------------
#define ADD2(d, a, b) \
    asm("add.rn.f32x2 %0, %1, %2;" : "=l"(d) : "l"(a), "l"(b))
#define MUL2(d, a, b) \
    asm("mul.rn.f32x2 %0, %1, %2;" : "=l"(d) : "l"(a), "l"(b))
#define FMA2(d, a, b, c) \
    asm("fma.rn.f32x2 %0, %1, %2, %3;" : "=l"(d) : "l"(a), "l"(b), "l"(c))
#define ABS2(d, a) \
    asm("and.b64 %0, %1, 0x7FFFFFFF7FFFFFFF;" : "=l"(d) : "l"(a))
#define UNPACK2(lo, hi, a) \
    asm("mov.b64 {%0, %1}, %2;" : "=f"(lo), "=f"(hi) : "l"(a))

__device__ __forceinline__ unsigned long long pack2(float lo, float hi) {
    unsigned long long r;
    asm("mov.b64 %0, {%1, %2};" : "=l"(r) : "f"(lo), "f"(hi));
    return r;
}

// ---------------------------------------------------------------------------
// Kernel 1: node transforms. 4 threads per node; thread q computes output
// columns [4q, 4q+4) of both feat_src and feat_dst.
// h == nullptr -> read g_h2 (layer 2 input). zero_acc: also zero accumulators.
// ---------------------------------------------------------------------------
__global__ void __launch_bounds__(256) node_transform4(
    const float* __restrict__ h,
    const float* __restrict__ Wsrc, const float* __restrict__ bsrc,
    const float* __restrict__ Wdst, const float* __restrict__ bdst,
    int zero_acc, int n_nodes)
{
    __shared__ float sWs[DD * DD];
    __shared__ float sWd[DD * DD];
    __shared__ float sbs[DD];
    __shared__ float sbd[DD];

    int tid = threadIdx.x;
    if (tid < DD * DD) { sWs[tid] = Wsrc[tid]; sWd[tid] = Wdst[tid]; }
    if (tid < DD)      { sbs[tid] = bsrc[tid]; sbd[tid] = bdst[tid]; }
    __syncthreads();

    int g = blockIdx.x * 256 + tid;
    int n = g >> 2;
    int q = g & 3;
    if (n >= n_nodes) return;

    const float* hrow = (h != nullptr) ? (h + (size_t)n * DD) : (g_h2 + (size_t)n * DD);
    const float4* hp = reinterpret_cast<const float4*>(hrow);
    float4 t0 = hp[0], t1 = hp[1], t2 = hp[2], t3 = hp[3];
    float hv[DD];
    hv[0]=t0.x;  hv[1]=t0.y;  hv[2]=t0.z;  hv[3]=t0.w;
    hv[4]=t1.x;  hv[5]=t1.y;  hv[6]=t1.z;  hv[7]=t1.w;
    hv[8]=t2.x;  hv[9]=t2.y;  hv[10]=t2.z; hv[11]=t2.w;
    hv[12]=t3.x; hv[13]=t3.y; hv[14]=t3.z; hv[15]=t3.w;

    int c0 = q * 4;
    float fs[4], fd[4];
#pragma unroll
    for (int j = 0; j < 4; j++) { fs[j] = sbs[c0 + j]; fd[j] = sbd[c0 + j]; }
#pragma unroll
    for (int i = 0; i < DD; i++) {
        float hi = hv[i];
#pragma unroll
        for (int j = 0; j < 4; j++) {
            fs[j] = fmaf(hi, sWs[i * DD + c0 + j], fs[j]);
            fd[j] = fmaf(hi, sWd[i * DD + c0 + j], fd[j]);
        }
    }

    reinterpret_cast<float4*>(g_featS + (size_t)n * DD)[q] =
        make_float4(fs[0], fs[1], fs[2], fs[3]);
    reinterpret_cast<float4*>(g_featD + (size_t)n * DD)[q] =
        make_float4(fd[0], fd[1], fd[2], fd[3]);
    if (zero_acc) {
        reinterpret_cast<float4*>(g_accum + (size_t)n * DD)[q] =
            make_float4(0.f, 0.f, 0.f, 0.f);
        if (q == 0) g_denom[n] = 0.f;
    }
}

// ---------------------------------------------------------------------------
// Kernel 2: per-edge attention pass, packed f32x2 arithmetic.
// lrelu(x,0.2) = 0.6x + 0.4|x|  ->  score = 0.6*dot(a,x) + 0.4*dot(a,|x|)
// exp without segment-max (softmax shift invariance; |score| small).
// Accumulate via red.global.add.v4.f32 + scalar red for denom.
// ---------------------------------------------------------------------------
__global__ void __launch_bounds__(256) edge_kernel(
    const int* __restrict__ src, const int* __restrict__ dst,
    const float* __restrict__ attn, int n_edges)
{
    __shared__ unsigned long long sa2[DD / 2];
    if (threadIdx.x < DD / 2) {
        float2 v = reinterpret_cast<const float2*>(attn)[threadIdx.x];
        sa2[threadIdx.x] = pack2(v.x, v.y);
    }
    __syncthreads();

    int e = blockIdx.x * 256 + threadIdx.x;
    if (e >= n_edges) return;

    int s = __ldg(&src[e]);
    int t = __ldg(&dst[e]);

    const ulonglong2* fsp = reinterpret_cast<const ulonglong2*>(g_featS + (size_t)s * DD);
    const ulonglong2* fdp = reinterpret_cast<const ulonglong2*>(g_featD + (size_t)t * DD);

    ulonglong2 A0 = fsp[0], A1 = fsp[1], A2 = fsp[2], A3 = fsp[3];
    ulonglong2 B0 = fdp[0], B1 = fdp[1], B2 = fdp[2], B3 = fdp[3];

    unsigned long long fa2[8] = {A0.x, A0.y, A1.x, A1.y, A2.x, A2.y, A3.x, A3.y};
    unsigned long long fb2[8] = {B0.x, B0.y, B1.x, B1.y, B2.x, B2.y, B3.x, B3.y};

    unsigned long long lin2 = 0ull;  // packed (0.0, 0.0)
    unsigned long long abs2 = 0ull;
#pragma unroll
    for (int k = 0; k < 8; k++) {
        unsigned long long x2, ax2, a2 = sa2[k];
        ADD2(x2, fa2[k], fb2[k]);
        ABS2(ax2, x2);
        FMA2(lin2, a2, x2, lin2);
        FMA2(abs2, a2, ax2, abs2);
    }

    // score2 = 0.6*lin2 + 0.4*abs2, then horizontal add
    unsigned int u06 = __float_as_uint(0.6f);
    unsigned int u04 = __float_as_uint(0.4f);
    unsigned long long K06 = (unsigned long long)u06 | ((unsigned long long)u06 << 32);
    unsigned long long K04 = (unsigned long long)u04 | ((unsigned long long)u04 << 32);
    unsigned long long c2;
    MUL2(c2, lin2, K06);
    FMA2(c2, abs2, K04, c2);
    float lo, hi;
    UNPACK2(lo, hi, c2);
    float ex = __expf(lo + hi);

    unsigned long long ex2 = pack2(ex, ex);
    float* ap = g_accum + (size_t)t * DD;
#pragma unroll
    for (int q = 0; q < 4; q++) {
        unsigned long long v2a, v2b;
        MUL2(v2a, ex2, fa2[2 * q]);
        MUL2(v2b, ex2, fa2[2 * q + 1]);
        float v0, v1, v2, v3;
        UNPACK2(v0, v1, v2a);
        UNPACK2(v2, v3, v2b);
        asm volatile("red.global.add.v4.f32 [%0], {%1, %2, %3, %4};"
                     :: "l"(ap + 4 * q), "f"(v0), "f"(v1), "f"(v2), "f"(v3)
                     : "memory");
    }
    atomicAdd(&g_denom[t], ex);
}

// ---------------------------------------------------------------------------
// Kernel 3: per-node finalize: rst = accum/denom (0 for empty segments),
// then leaky_relu(0.01). Writes to g_h2 (layer 1) or to out (layer 2).
// zero_next: re-zero accum/denom for the next layer (lines already in cache).
// ---------------------------------------------------------------------------
__global__ void __launch_bounds__(256) finalize_kernel(float* __restrict__ out,
                                                       int to_scratch, int zero_next,
                                                       int n_nodes)
{
    int n = blockIdx.x * blockDim.x + threadIdx.x;
    if (n >= n_nodes) return;

    float dn = g_denom[n];
    float inv = (dn > 0.f) ? (1.0f / dn) : 0.0f;

    float4* ap = reinterpret_cast<float4*>(g_accum + (size_t)n * DD);
    float4* op = to_scratch
                     ? reinterpret_cast<float4*>(g_h2 + (size_t)n * DD)
                     : reinterpret_cast<float4*>(out + (size_t)n * DD);
#pragma unroll
    for (int q = 0; q < 4; q++) {
        float4 a = ap[q];
        float r0 = a.x * inv, r1 = a.y * inv, r2 = a.z * inv, r3 = a.w * inv;
        r0 = (r0 > 0.f) ? r0 : ACT_SLOPE * r0;
        r1 = (r1 > 0.f) ? r1 : ACT_SLOPE * r1;
        r2 = (r2 > 0.f) ? r2 : ACT_SLOPE * r2;
        r3 = (r3 > 0.f) ? r3 : ACT_SLOPE * r3;
        op[q] = make_float4(r0, r1, r2, r3);
        if (zero_next) ap[q] = make_float4(0.f, 0.f, 0.f, 0.f);
    }
    if (zero_next) g_denom[n] = 0.f;
}

// ---------------------------------------------------------------------------
extern "C" void kernel_launch(void* const* d_in, const int* in_sizes, int n_in,
                              void* d_out, int out_size)
{
    const float* emb   = (const float*)d_in[0];
    const int*   src1  = (const int*)d_in[1];
    const int*   dst1  = (const int*)d_in[2];
    const int*   src2  = (const int*)d_in[3];
    const int*   dst2  = (const int*)d_in[4];
    const float* Wsrc1 = (const float*)d_in[5];
    const float* bsrc1 = (const float*)d_in[6];
    const float* Wdst1 = (const float*)d_in[7];
    const float* bdst1 = (const float*)d_in[8];
    const float* attn1 = (const float*)d_in[9];
    const float* Wsrc2 = (const float*)d_in[10];
    const float* bsrc2 = (const float*)d_in[11];
    const float* Wdst2 = (const float*)d_in[12];
    const float* bdst2 = (const float*)d_in[13];
    const float* attn2 = (const float*)d_in[14];

    int n_nodes  = in_sizes[0] / DD;
    int n_edges1 = in_sizes[1];
    int n_edges2 = in_sizes[3];
    float* out = (float*)d_out;

    int nblk4 = (n_nodes * 4 + 255) / 256;
    int nblk  = (n_nodes + 255) / 256;
    int eblk1 = (n_edges1 + 255) / 256;
    int eblk2 = (n_edges2 + 255) / 256;

    // Layer 1 (transform zeroes accumulators)
    node_transform4<<<nblk4, 256>>>(emb, Wsrc1, bsrc1, Wdst1, bdst1, 1, n_nodes);
    edge_kernel<<<eblk1, 256>>>(src1, dst1, attn1, n_edges1);
    // finalize writes g_h2 AND re-zeroes accumulators for layer 2
    finalize_kernel<<<nblk, 256>>>(out, /*to_scratch=*/1, /*zero_next=*/1, n_nodes);

    // Layer 2 (transform does NOT zero; finalize1 already did)
    node_transform4<<<nblk4, 256>>>(nullptr, Wsrc2, bsrc2, Wdst2, bdst2, 0, n_nodes);
    edge_kernel<<<eblk2, 256>>>(src2, dst2, attn2, n_edges2);
    finalize_kernel<<<nblk, 256>>>(out, /*to_scratch=*/0, /*zero_next=*/0, n_nodes);
}

// round 4
// speedup vs baseline: 1.3177x; 1.1286x over previous
#include <cuda_runtime.h>
#include <cstdint>

#define NN 100000
#define EE 3200000
#define DD 16
#define ATTN_SLOPE 0.2f
#define ACT_SLOPE 0.01f

// Scratch (device globals: allocation-free rule). 256B-aligned for LDG.256.
__device__ __align__(256) float g_featS[NN * DD];
__device__ __align__(256) float g_featD[NN * DD];
__device__ __align__(256) float g_accum[NN * DD];
__device__ __align__(256) float g_denom[NN];
__device__ __align__(256) float g_h2[NN * DD];

// 256-bit global load (sm_100+): one LDG.E.256 for 8 floats.
__device__ __forceinline__ void ldg_v8(const float* __restrict__ p, float* f) {
    asm("ld.global.nc.v8.f32 {%0,%1,%2,%3,%4,%5,%6,%7}, [%8];"
        : "=f"(f[0]), "=f"(f[1]), "=f"(f[2]), "=f"(f[3]),
          "=f"(f[4]), "=f"(f[5]), "=f"(f[6]), "=f"(f[7])
        : "l"(p));
}

// ---------------------------------------------------------------------------
// Kernel 1: node transforms. 4 threads per node; thread q computes output
// columns [4q, 4q+4) of both feat_src and feat_dst.
// h == nullptr -> read g_h2 (layer 2 input). zero_acc: also zero accumulators.
// ---------------------------------------------------------------------------
__global__ void __launch_bounds__(256) node_transform4(
    const float* __restrict__ h,
    const float* __restrict__ Wsrc, const float* __restrict__ bsrc,
    const float* __restrict__ Wdst, const float* __restrict__ bdst,
    int zero_acc, int n_nodes)
{
    __shared__ float sWs[DD * DD];
    __shared__ float sWd[DD * DD];
    __shared__ float sbs[DD];
    __shared__ float sbd[DD];

    int tid = threadIdx.x;
    if (tid < DD * DD) { sWs[tid] = Wsrc[tid]; sWd[tid] = Wdst[tid]; }
    if (tid < DD)      { sbs[tid] = bsrc[tid]; sbd[tid] = bdst[tid]; }
    __syncthreads();

    int g = blockIdx.x * 256 + tid;
    int n = g >> 2;
    int q = g & 3;
    if (n >= n_nodes) return;

    const float* hrow = (h != nullptr) ? (h + (size_t)n * DD) : (g_h2 + (size_t)n * DD);
    float hv[DD];
    ldg_v8(hrow, hv);
    ldg_v8(hrow + 8, hv + 8);

    int c0 = q * 4;
    float fs[4], fd[4];
#pragma unroll
    for (int j = 0; j < 4; j++) { fs[j] = sbs[c0 + j]; fd[j] = sbd[c0 + j]; }
#pragma unroll
    for (int i = 0; i < DD; i++) {
        float hi = hv[i];
#pragma unroll
        for (int j = 0; j < 4; j++) {
            fs[j] = fmaf(hi, sWs[i * DD + c0 + j], fs[j]);
            fd[j] = fmaf(hi, sWd[i * DD + c0 + j], fd[j]);
        }
    }

    reinterpret_cast<float4*>(g_featS + (size_t)n * DD)[q] =
        make_float4(fs[0], fs[1], fs[2], fs[3]);
    reinterpret_cast<float4*>(g_featD + (size_t)n * DD)[q] =
        make_float4(fd[0], fd[1], fd[2], fd[3]);
    if (zero_acc) {
        reinterpret_cast<float4*>(g_accum + (size_t)n * DD)[q] =
            make_float4(0.f, 0.f, 0.f, 0.f);
        if (q == 0) g_denom[n] = 0.f;
    }
}

// ---------------------------------------------------------------------------
// Per-edge core: gather (2x LDG.256 per row), score, exp, scatter reds.
// ---------------------------------------------------------------------------
__device__ __forceinline__ void process_edge(int s, int t, const float* a)
{
    const float* ps = g_featS + (size_t)s * DD;
    const float* pt = g_featD + (size_t)t * DD;
    float fa[DD], fb[DD];
    ldg_v8(ps, fa);
    ldg_v8(ps + 8, fa + 8);
    ldg_v8(pt, fb);
    ldg_v8(pt + 8, fb + 8);

    float sc = 0.f;
#pragma unroll
    for (int k = 0; k < DD; k++) {
        float x = fa[k] + fb[k];
        x = (x > 0.f) ? x : ATTN_SLOPE * x;
        sc = fmaf(a[k], x, sc);
    }
    float ex = __expf(sc);  // no segment-max: softmax shift invariance, |sc| small

    float* ap = g_accum + (size_t)t * DD;
#pragma unroll
    for (int q = 0; q < 4; q++) {
        float v0 = ex * fa[4*q + 0];
        float v1 = ex * fa[4*q + 1];
        float v2 = ex * fa[4*q + 2];
        float v3 = ex * fa[4*q + 3];
        asm volatile("red.global.add.v4.f32 [%0], {%1, %2, %3, %4};"
                     :: "l"(ap + 4 * q), "f"(v0), "f"(v1), "f"(v2), "f"(v3)
                     : "memory");
    }
    atomicAdd(&g_denom[t], ex);
}

// ---------------------------------------------------------------------------
// Kernel 2: 4 edges per thread; vectorized int4 index loads.
// ---------------------------------------------------------------------------
__global__ void __launch_bounds__(256) edge_kernel4(
    const int* __restrict__ src, const int* __restrict__ dst,
    const float* __restrict__ attn, int n_quads)
{
    __shared__ float sa[DD];
    if (threadIdx.x < DD) sa[threadIdx.x] = attn[threadIdx.x];
    __syncthreads();
    float a[DD];
#pragma unroll
    for (int k = 0; k < DD; k++) a[k] = sa[k];

    int i = blockIdx.x * 256 + threadIdx.x;
    if (i >= n_quads) return;

    int4 s4 = reinterpret_cast<const int4*>(src)[i];
    int4 t4 = reinterpret_cast<const int4*>(dst)[i];

    process_edge(s4.x, t4.x, a);
    process_edge(s4.y, t4.y, a);
    process_edge(s4.z, t4.z, a);
    process_edge(s4.w, t4.w, a);
}

// Remainder edges (n_edges % 4), scalar.
__global__ void __launch_bounds__(64) edge_kernel_rem(
    const int* __restrict__ src, const int* __restrict__ dst,
    const float* __restrict__ attn, int base, int n_edges)
{
    float a[DD];
#pragma unroll
    for (int k = 0; k < DD; k++) a[k] = __ldg(&attn[k]);
    int e = base + blockIdx.x * 64 + threadIdx.x;
    if (e < n_edges) process_edge(__ldg(&src[e]), __ldg(&dst[e]), a);
}

// ---------------------------------------------------------------------------
// Kernel 3: finalize: rst = accum/denom (0 for empty), leaky_relu(0.01).
// zero_next: re-zero accum/denom for the next layer.
// ---------------------------------------------------------------------------
__global__ void __launch_bounds__(256) finalize_kernel(float* __restrict__ out,
                                                       int to_scratch, int zero_next,
                                                       int n_nodes)
{
    int n = blockIdx.x * blockDim.x + threadIdx.x;
    if (n >= n_nodes) return;

    float dn = g_denom[n];
    float inv = (dn > 0.f) ? (1.0f / dn) : 0.0f;

    float4* ap = reinterpret_cast<float4*>(g_accum + (size_t)n * DD);
    float4* op = to_scratch
                     ? reinterpret_cast<float4*>(g_h2 + (size_t)n * DD)
                     : reinterpret_cast<float4*>(out + (size_t)n * DD);
#pragma unroll
    for (int q = 0; q < 4; q++) {
        float4 v = ap[q];
        float r0 = v.x * inv, r1 = v.y * inv, r2 = v.z * inv, r3 = v.w * inv;
        r0 = (r0 > 0.f) ? r0 : ACT_SLOPE * r0;
        r1 = (r1 > 0.f) ? r1 : ACT_SLOPE * r1;
        r2 = (r2 > 0.f) ? r2 : ACT_SLOPE * r2;
        r3 = (r3 > 0.f) ? r3 : ACT_SLOPE * r3;
        op[q] = make_float4(r0, r1, r2, r3);
        if (zero_next) ap[q] = make_float4(0.f, 0.f, 0.f, 0.f);
    }
    if (zero_next) g_denom[n] = 0.f;
}

// ---------------------------------------------------------------------------
extern "C" void kernel_launch(void* const* d_in, const int* in_sizes, int n_in,
                              void* d_out, int out_size)
{
    const float* emb   = (const float*)d_in[0];
    const int*   src1  = (const int*)d_in[1];
    const int*   dst1  = (const int*)d_in[2];
    const int*   src2  = (const int*)d_in[3];
    const int*   dst2  = (const int*)d_in[4];
    const float* Wsrc1 = (const float*)d_in[5];
    const float* bsrc1 = (const float*)d_in[6];
    const float* Wdst1 = (const float*)d_in[7];
    const float* bdst1 = (const float*)d_in[8];
    const float* attn1 = (const float*)d_in[9];
    const float* Wsrc2 = (const float*)d_in[10];
    const float* bsrc2 = (const float*)d_in[11];
    const float* Wdst2 = (const float*)d_in[12];
    const float* bdst2 = (const float*)d_in[13];
    const float* attn2 = (const float*)d_in[14];

    int n_nodes  = in_sizes[0] / DD;
    int n_edges1 = in_sizes[1];
    int n_edges2 = in_sizes[3];
    float* out = (float*)d_out;

    int nblk4 = (n_nodes * 4 + 255) / 256;
    int nblk  = (n_nodes + 255) / 256;

    int nq1 = n_edges1 / 4, rem1 = n_edges1 - nq1 * 4;
    int nq2 = n_edges2 / 4, rem2 = n_edges2 - nq2 * 4;
    int qblk1 = (nq1 + 255) / 256;
    int qblk2 = (nq2 + 255) / 256;

    // Layer 1 (transform zeroes accumulators)
    node_transform4<<<nblk4, 256>>>(emb, Wsrc1, bsrc1, Wdst1, bdst1, 1, n_nodes);
    if (nq1 > 0)  edge_kernel4<<<qblk1, 256>>>(src1, dst1, attn1, nq1);
    if (rem1 > 0) edge_kernel_rem<<<1, 64>>>(src1, dst1, attn1, nq1 * 4, n_edges1);
    // finalize writes g_h2 AND re-zeroes accumulators for layer 2
    finalize_kernel<<<nblk, 256>>>(out, /*to_scratch=*/1, /*zero_next=*/1, n_nodes);

    // Layer 2
    node_transform4<<<nblk4, 256>>>(nullptr, Wsrc2, bsrc2, Wdst2, bdst2, 0, n_nodes);
    if (nq2 > 0)  edge_kernel4<<<qblk2, 256>>>(src2, dst2, attn2, nq2);
    if (rem2 > 0) edge_kernel_rem<<<1, 64>>>(src2, dst2, attn2, nq2 * 4, n_edges2);
    finalize_kernel<<<nblk, 256>>>(out, /*to_scratch=*/0, /*zero_next=*/0, n_nodes);
}

// round 5
// speedup vs baseline: 2.0042x; 1.5209x over previous
#include <cuda_runtime.h>
#include <cstdint>

#define NN 100000
#define EE 3200000
#define DD 16
#define ATTN_SLOPE 0.2f
#define ACT_SLOPE 0.01f

// Scratch (device globals: allocation-free rule). 256B-aligned.
__device__ __align__(256) float g_featS[NN * DD];
__device__ __align__(256) float g_featD[NN * DD];
__device__ __align__(256) float g_accum[NN * DD];
__device__ __align__(256) float g_denom[NN];
__device__ __align__(256) float g_h2[NN * DD];

// 256-bit global load (sm_100+): one LDG.E.256 for 8 floats.
__device__ __forceinline__ void ldg_v8(const float* __restrict__ p, float* f) {
    asm("ld.global.nc.v8.f32 {%0,%1,%2,%3,%4,%5,%6,%7}, [%8];"
        : "=f"(f[0]), "=f"(f[1]), "=f"(f[2]), "=f"(f[3]),
          "=f"(f[4]), "=f"(f[5]), "=f"(f[6]), "=f"(f[7])
        : "l"(p));
}

__device__ __forceinline__ float4 ldg_v4(const float* __restrict__ p) {
    float4 v;
    asm("ld.global.nc.v4.f32 {%0,%1,%2,%3}, [%4];"
        : "=f"(v.x), "=f"(v.y), "=f"(v.z), "=f"(v.w) : "l"(p));
    return v;
}

// ---------------------------------------------------------------------------
// Kernel 1: node transforms. 4 threads per node; thread q computes output
// columns [4q, 4q+4) of both feat_src and feat_dst.
// h == nullptr -> read g_h2 (layer 2 input). zero_acc: also zero accumulators.
// ---------------------------------------------------------------------------
__global__ void __launch_bounds__(256) node_transform4(
    const float* __restrict__ h,
    const float* __restrict__ Wsrc, const float* __restrict__ bsrc,
    const float* __restrict__ Wdst, const float* __restrict__ bdst,
    int zero_acc, int n_nodes)
{
    __shared__ float sWs[DD * DD];
    __shared__ float sWd[DD * DD];
    __shared__ float sbs[DD];
    __shared__ float sbd[DD];

    int tid = threadIdx.x;
    if (tid < DD * DD) { sWs[tid] = Wsrc[tid]; sWd[tid] = Wdst[tid]; }
    if (tid < DD)      { sbs[tid] = bsrc[tid]; sbd[tid] = bdst[tid]; }
    __syncthreads();

    int g = blockIdx.x * 256 + tid;
    int n = g >> 2;
    int q = g & 3;
    if (n >= n_nodes) return;

    const float* hrow = (h != nullptr) ? (h + (size_t)n * DD) : (g_h2 + (size_t)n * DD);
    float hv[DD];
    ldg_v8(hrow, hv);
    ldg_v8(hrow + 8, hv + 8);

    int c0 = q * 4;
    float fs[4], fd[4];
#pragma unroll
    for (int j = 0; j < 4; j++) { fs[j] = sbs[c0 + j]; fd[j] = sbd[c0 + j]; }
#pragma unroll
    for (int i = 0; i < DD; i++) {
        float hi = hv[i];
#pragma unroll
        for (int j = 0; j < 4; j++) {
            fs[j] = fmaf(hi, sWs[i * DD + c0 + j], fs[j]);
            fd[j] = fmaf(hi, sWd[i * DD + c0 + j], fd[j]);
        }
    }

    reinterpret_cast<float4*>(g_featS + (size_t)n * DD)[q] =
        make_float4(fs[0], fs[1], fs[2], fs[3]);
    reinterpret_cast<float4*>(g_featD + (size_t)n * DD)[q] =
        make_float4(fd[0], fd[1], fd[2], fd[3]);
    if (zero_acc) {
        reinterpret_cast<float4*>(g_accum + (size_t)n * DD)[q] =
            make_float4(0.f, 0.f, 0.f, 0.f);
        if (q == 0) g_denom[n] = 0.f;
    }
}

// ---------------------------------------------------------------------------
// Kernel 2: warp-cooperative edge pass. 4 lanes per edge (8 edges/warp/iter).
// Lane p of an edge-group handles feature chunk [4p, 4p+4).
// Gathers and red.v4 scatters thus coalesce 8 edges per warp instruction:
// ~4 L1tex wavefronts/edge instead of ~9 for the thread-per-edge version.
// score = 0.6*dot(a,x) + 0.4*dot(a,|x|)  (== dot(a, lrelu(x, 0.2)))
// No segment-max (softmax shift invariance; scores are ~N(0,1)).
// ---------------------------------------------------------------------------
__global__ void __launch_bounds__(256) edge_kernel_coop(
    const int* __restrict__ src, const int* __restrict__ dst,
    const float* __restrict__ attn, int n_edges)
{
    __shared__ float sa[DD];
    if (threadIdx.x < DD) sa[threadIdx.x] = attn[threadIdx.x];
    __syncthreads();

    int lane = threadIdx.x & 31;
    int p = lane & 3;               // chunk index within edge
    int sub = lane >> 2;            // edge index within warp (0..7)
    int warp_global = (blockIdx.x * 256 + threadIdx.x) >> 5;

    // per-lane attention coefficients for chunk p
    float a0 = sa[p * 4 + 0], a1 = sa[p * 4 + 1];
    float a2 = sa[p * 4 + 2], a3 = sa[p * 4 + 3];

    int e = warp_global * 8 + sub;
    bool valid = (e < n_edges);
    int ec = valid ? e : 0;

    int s = __ldg(&src[ec]);
    int t = __ldg(&dst[ec]);

    float4 fa = ldg_v4(g_featS + (size_t)s * DD + p * 4);
    float4 fb = ldg_v4(g_featD + (size_t)t * DD + p * 4);

    // partial score over this lane's 4 elements
    float x0 = fa.x + fb.x, x1 = fa.y + fb.y, x2 = fa.z + fb.z, x3 = fa.w + fb.w;
    float lin = a0 * x0;
    lin = fmaf(a1, x1, lin);
    lin = fmaf(a2, x2, lin);
    lin = fmaf(a3, x3, lin);
    float ab = a0 * fabsf(x0);
    ab = fmaf(a1, fabsf(x1), ab);
    ab = fmaf(a2, fabsf(x2), ab);
    ab = fmaf(a3, fabsf(x3), ab);
    float part = fmaf(0.6f, lin, 0.4f * ab);

    // reduce across the 4-lane group
    part += __shfl_xor_sync(0xffffffffu, part, 1);
    part += __shfl_xor_sync(0xffffffffu, part, 2);

    float ex = __expf(part);

    if (valid) {
        float v0 = ex * fa.x, v1 = ex * fa.y, v2 = ex * fa.z, v3 = ex * fa.w;
        float* ap = g_accum + (size_t)t * DD + p * 4;
        asm volatile("red.global.add.v4.f32 [%0], {%1, %2, %3, %4};"
                     :: "l"(ap), "f"(v0), "f"(v1), "f"(v2), "f"(v3)
                     : "memory");
        if (p == 0) atomicAdd(&g_denom[t], ex);
    }
}

// ---------------------------------------------------------------------------
// Kernel 3: finalize: rst = accum/denom (0 for empty), leaky_relu(0.01).
// zero_next: re-zero accum/denom for the next layer.
// ---------------------------------------------------------------------------
__global__ void __launch_bounds__(256) finalize_kernel(float* __restrict__ out,
                                                       int to_scratch, int zero_next,
                                                       int n_nodes)
{
    int n = blockIdx.x * blockDim.x + threadIdx.x;
    if (n >= n_nodes) return;

    float dn = g_denom[n];
    float inv = (dn > 0.f) ? (1.0f / dn) : 0.0f;

    float4* ap = reinterpret_cast<float4*>(g_accum + (size_t)n * DD);
    float4* op = to_scratch
                     ? reinterpret_cast<float4*>(g_h2 + (size_t)n * DD)
                     : reinterpret_cast<float4*>(out + (size_t)n * DD);
#pragma unroll
    for (int q = 0; q < 4; q++) {
        float4 v = ap[q];
        float r0 = v.x * inv, r1 = v.y * inv, r2 = v.z * inv, r3 = v.w * inv;
        r0 = (r0 > 0.f) ? r0 : ACT_SLOPE * r0;
        r1 = (r1 > 0.f) ? r1 : ACT_SLOPE * r1;
        r2 = (r2 > 0.f) ? r2 : ACT_SLOPE * r2;
        r3 = (r3 > 0.f) ? r3 : ACT_SLOPE * r3;
        op[q] = make_float4(r0, r1, r2, r3);
        if (zero_next) ap[q] = make_float4(0.f, 0.f, 0.f, 0.f);
    }
    if (zero_next) g_denom[n] = 0.f;
}

// ---------------------------------------------------------------------------
extern "C" void kernel_launch(void* const* d_in, const int* in_sizes, int n_in,
                              void* d_out, int out_size)
{
    const float* emb   = (const float*)d_in[0];
    const int*   src1  = (const int*)d_in[1];
    const int*   dst1  = (const int*)d_in[2];
    const int*   src2  = (const int*)d_in[3];
    const int*   dst2  = (const int*)d_in[4];
    const float* Wsrc1 = (const float*)d_in[5];
    const float* bsrc1 = (const float*)d_in[6];
    const float* Wdst1 = (const float*)d_in[7];
    const float* bdst1 = (const float*)d_in[8];
    const float* attn1 = (const float*)d_in[9];
    const float* Wsrc2 = (const float*)d_in[10];
    const float* bsrc2 = (const float*)d_in[11];
    const float* Wdst2 = (const float*)d_in[12];
    const float* bdst2 = (const float*)d_in[13];
    const float* attn2 = (const float*)d_in[14];

    int n_nodes  = in_sizes[0] / DD;
    int n_edges1 = in_sizes[1];
    int n_edges2 = in_sizes[3];
    float* out = (float*)d_out;

    int nblk4 = (n_nodes * 4 + 255) / 256;
    int nblk  = (n_nodes + 255) / 256;

    // 64 edges per 256-thread block (4 lanes/edge)
    int eblk1 = (n_edges1 + 63) / 64;
    int eblk2 = (n_edges2 + 63) / 64;

    // Layer 1 (transform zeroes accumulators)
    node_transform4<<<nblk4, 256>>>(emb, Wsrc1, bsrc1, Wdst1, bdst1, 1, n_nodes);
    edge_kernel_coop<<<eblk1, 256>>>(src1, dst1, attn1, n_edges1);
    // finalize writes g_h2 AND re-zeroes accumulators for layer 2
    finalize_kernel<<<nblk, 256>>>(out, /*to_scratch=*/1, /*zero_next=*/1, n_nodes);

    // Layer 2
    node_transform4<<<nblk4, 256>>>(nullptr, Wsrc2, bsrc2, Wdst2, bdst2, 0, n_nodes);
    edge_kernel_coop<<<eblk2, 256>>>(src2, dst2, attn2, n_edges2);
    finalize_kernel<<<nblk, 256>>>(out, /*to_scratch=*/0, /*zero_next=*/0, n_nodes);
}

// round 6
// speedup vs baseline: 2.1298x; 1.0627x over previous
#include <cuda_runtime.h>
#include <cuda_fp16.h>
#include <cstdint>

#define NN 100000
#define EE 3200000
#define DD 16
#define ACT_SLOPE 0.01f

// Scratch (device globals: allocation-free rule). 256B-aligned.
__device__ __align__(256) float  g_featS[NN * DD];   // fp32: accumulated
__device__ __align__(256) __half g_featDh[NN * DD];  // fp16: score-only
__device__ __align__(256) float  g_accum[NN * DD];
__device__ __align__(256) float  g_denom[NN];

// 256-bit global load (sm_100+): one LDG.E.256 for 8 floats.
__device__ __forceinline__ void ldg_v8(const float* __restrict__ p, float* f) {
    asm("ld.global.nc.v8.f32 {%0,%1,%2,%3,%4,%5,%6,%7}, [%8];"
        : "=f"(f[0]), "=f"(f[1]), "=f"(f[2]), "=f"(f[3]),
          "=f"(f[4]), "=f"(f[5]), "=f"(f[6]), "=f"(f[7])
        : "l"(p));
}

__device__ __forceinline__ float4 ldg_v4(const float* __restrict__ p) {
    float4 v;
    asm("ld.global.nc.v4.f32 {%0,%1,%2,%3}, [%4];"
        : "=f"(v.x), "=f"(v.y), "=f"(v.z), "=f"(v.w) : "l"(p));
    return v;
}

__device__ __forceinline__ uint2 ldg_u2(const void* __restrict__ p) {
    uint2 v;
    asm("ld.global.nc.v2.u32 {%0,%1}, [%2];" : "=r"(v.x), "=r"(v.y) : "l"(p));
    return v;
}

// Shared transform core: given h row (16 floats) and weights in smem, thread q
// produces chunk [4q,4q+4) of featS (fp32) and featDh (fp16), zeroes accum.
__device__ __forceinline__ void transform_store(
    const float* hv, const float* sWs, const float* sWd,
    const float* sbs, const float* sbd, int n, int q)
{
    int c0 = q * 4;
    float fs[4], fd[4];
#pragma unroll
    for (int j = 0; j < 4; j++) { fs[j] = sbs[c0 + j]; fd[j] = sbd[c0 + j]; }
#pragma unroll
    for (int i = 0; i < DD; i++) {
        float hi = hv[i];
#pragma unroll
        for (int j = 0; j < 4; j++) {
            fs[j] = fmaf(hi, sWs[i * DD + c0 + j], fs[j]);
            fd[j] = fmaf(hi, sWd[i * DD + c0 + j], fd[j]);
        }
    }
    reinterpret_cast<float4*>(g_featS + (size_t)n * DD)[q] =
        make_float4(fs[0], fs[1], fs[2], fs[3]);
    __half2 d0 = __floats2half2_rn(fd[0], fd[1]);
    __half2 d1 = __floats2half2_rn(fd[2], fd[3]);
    uint2 st;
    st.x = *reinterpret_cast<unsigned int*>(&d0);
    st.y = *reinterpret_cast<unsigned int*>(&d1);
    *reinterpret_cast<uint2*>(g_featDh + (size_t)n * DD + q * 4) = st;
    // zero accumulators for the upcoming edge pass
    reinterpret_cast<float4*>(g_accum + (size_t)n * DD)[q] =
        make_float4(0.f, 0.f, 0.f, 0.f);
    if (q == 0) g_denom[n] = 0.f;
}

// ---------------------------------------------------------------------------
// Kernel 1: layer-1 transform from embedding. 4 threads per node.
// ---------------------------------------------------------------------------
__global__ void __launch_bounds__(256) transform1_k(
    const float* __restrict__ h,
    const float* __restrict__ Wsrc, const float* __restrict__ bsrc,
    const float* __restrict__ Wdst, const float* __restrict__ bdst,
    int n_nodes)
{
    __shared__ float sWs[DD * DD], sWd[DD * DD], sbs[DD], sbd[DD];
    int tid = threadIdx.x;
    if (tid < DD * DD) { sWs[tid] = Wsrc[tid]; sWd[tid] = Wdst[tid]; }
    if (tid < DD)      { sbs[tid] = bsrc[tid]; sbd[tid] = bdst[tid]; }
    __syncthreads();

    int g = blockIdx.x * 256 + tid;
    int n = g >> 2, q = g & 3;
    if (n >= n_nodes) return;

    float hv[DD];
    ldg_v8(h + (size_t)n * DD, hv);
    ldg_v8(h + (size_t)n * DD + 8, hv + 8);
    transform_store(hv, sWs, sWd, sbs, sbd, n, q);
}

// ---------------------------------------------------------------------------
// Kernel 2 (fused): layer-1 finalize + layer-2 transform. 4 threads per node.
// h2 = leaky_relu(accum/denom, 0.01) computed in registers; accum re-zeroed.
// Safe: the 4 threads of a node are in one warp; loads precede stores in the
// lockstep instruction stream.
// ---------------------------------------------------------------------------
__global__ void __launch_bounds__(256) transform2_fused_k(
    const float* __restrict__ Wsrc, const float* __restrict__ bsrc,
    const float* __restrict__ Wdst, const float* __restrict__ bdst,
    int n_nodes)
{
    __shared__ float sWs[DD * DD], sWd[DD * DD], sbs[DD], sbd[DD];
    int tid = threadIdx.x;
    if (tid < DD * DD) { sWs[tid] = Wsrc[tid]; sWd[tid] = Wdst[tid]; }
    if (tid < DD)      { sbs[tid] = bsrc[tid]; sbd[tid] = bdst[tid]; }
    __syncthreads();

    int g = blockIdx.x * 256 + tid;
    int n = g >> 2, q = g & 3;
    if (n >= n_nodes) return;

    float dn = g_denom[n];
    float inv = (dn > 0.f) ? (1.0f / dn) : 0.0f;

    float hv[DD];
    ldg_v8(g_accum + (size_t)n * DD, hv);
    ldg_v8(g_accum + (size_t)n * DD + 8, hv + 8);
#pragma unroll
    for (int k = 0; k < DD; k++) {
        float r = hv[k] * inv;
        hv[k] = (r > 0.f) ? r : ACT_SLOPE * r;
    }
    transform_store(hv, sWs, sWd, sbs, sbd, n, q);
}

// ---------------------------------------------------------------------------
// Kernel 3: warp-cooperative edge pass. 4 lanes per edge (8 edges/warp).
// featS fp32 (2 sectors), featD fp16 (1 sector). Scatter via red.v4 + denom.
// score = 0.6*dot(a,x) + 0.4*dot(a,|x|)  (== dot(a, lrelu(x, 0.2)))
// No segment-max (softmax shift invariance; scores ~N(0,1)).
// ---------------------------------------------------------------------------
__global__ void __launch_bounds__(256) edge_kernel_coop(
    const int* __restrict__ src, const int* __restrict__ dst,
    const float* __restrict__ attn, int n_edges)
{
    __shared__ float sa[DD];
    if (threadIdx.x < DD) sa[threadIdx.x] = attn[threadIdx.x];
    __syncthreads();

    int lane = threadIdx.x & 31;
    int p = lane & 3;
    int sub = lane >> 2;
    int warp_global = (blockIdx.x * 256 + threadIdx.x) >> 5;

    float a0 = sa[p * 4 + 0], a1 = sa[p * 4 + 1];
    float a2 = sa[p * 4 + 2], a3 = sa[p * 4 + 3];

    int e = warp_global * 8 + sub;
    bool valid = (e < n_edges);
    int ec = valid ? e : 0;

    int s = __ldg(&src[ec]);
    int t = __ldg(&dst[ec]);

    float4 fa = ldg_v4(g_featS + (size_t)s * DD + p * 4);
    uint2 hb = ldg_u2(g_featDh + (size_t)t * DD + p * 4);
    float2 b01 = __half22float2(*reinterpret_cast<__half2*>(&hb.x));
    float2 b23 = __half22float2(*reinterpret_cast<__half2*>(&hb.y));

    float x0 = fa.x + b01.x, x1 = fa.y + b01.y;
    float x2 = fa.z + b23.x, x3 = fa.w + b23.y;
    float lin = a0 * x0;
    lin = fmaf(a1, x1, lin);
    lin = fmaf(a2, x2, lin);
    lin = fmaf(a3, x3, lin);
    float ab = a0 * fabsf(x0);
    ab = fmaf(a1, fabsf(x1), ab);
    ab = fmaf(a2, fabsf(x2), ab);
    ab = fmaf(a3, fabsf(x3), ab);
    float part = fmaf(0.6f, lin, 0.4f * ab);

    part += __shfl_xor_sync(0xffffffffu, part, 1);
    part += __shfl_xor_sync(0xffffffffu, part, 2);

    float ex = __expf(part);

    if (valid) {
        float v0 = ex * fa.x, v1 = ex * fa.y, v2 = ex * fa.z, v3 = ex * fa.w;
        float* ap = g_accum + (size_t)t * DD + p * 4;
        asm volatile("red.global.add.v4.f32 [%0], {%1, %2, %3, %4};"
                     :: "l"(ap), "f"(v0), "f"(v1), "f"(v2), "f"(v3)
                     : "memory");
        if (p == 0) atomicAdd(&g_denom[t], ex);
    }
}

// ---------------------------------------------------------------------------
// Kernel 4: layer-2 finalize -> d_out.
// ---------------------------------------------------------------------------
__global__ void __launch_bounds__(256) finalize2_k(float* __restrict__ out, int n_nodes)
{
    int n = blockIdx.x * blockDim.x + threadIdx.x;
    if (n >= n_nodes) return;

    float dn = g_denom[n];
    float inv = (dn > 0.f) ? (1.0f / dn) : 0.0f;

    const float4* ap = reinterpret_cast<const float4*>(g_accum + (size_t)n * DD);
    float4* op = reinterpret_cast<float4*>(out + (size_t)n * DD);
#pragma unroll
    for (int q = 0; q < 4; q++) {
        float4 v = ap[q];
        float r0 = v.x * inv, r1 = v.y * inv, r2 = v.z * inv, r3 = v.w * inv;
        r0 = (r0 > 0.f) ? r0 : ACT_SLOPE * r0;
        r1 = (r1 > 0.f) ? r1 : ACT_SLOPE * r1;
        r2 = (r2 > 0.f) ? r2 : ACT_SLOPE * r2;
        r3 = (r3 > 0.f) ? r3 : ACT_SLOPE * r3;
        op[q] = make_float4(r0, r1, r2, r3);
    }
}

// ---------------------------------------------------------------------------
extern "C" void kernel_launch(void* const* d_in, const int* in_sizes, int n_in,
                              void* d_out, int out_size)
{
    const float* emb   = (const float*)d_in[0];
    const int*   src1  = (const int*)d_in[1];
    const int*   dst1  = (const int*)d_in[2];
    const int*   src2  = (const int*)d_in[3];
    const int*   dst2  = (const int*)d_in[4];
    const float* Wsrc1 = (const float*)d_in[5];
    const float* bsrc1 = (const float*)d_in[6];
    const float* Wdst1 = (const float*)d_in[7];
    const float* bdst1 = (const float*)d_in[8];
    const float* attn1 = (const float*)d_in[9];
    const float* Wsrc2 = (const float*)d_in[10];
    const float* bsrc2 = (const float*)d_in[11];
    const float* Wdst2 = (const float*)d_in[12];
    const float* bdst2 = (const float*)d_in[13];
    const float* attn2 = (const float*)d_in[14];

    int n_nodes  = in_sizes[0] / DD;
    int n_edges1 = in_sizes[1];
    int n_edges2 = in_sizes[3];
    float* out = (float*)d_out;

    int nblk4 = (n_nodes * 4 + 255) / 256;
    int nblk  = (n_nodes + 255) / 256;
    int eblk1 = (n_edges1 + 63) / 64;   // 64 edges per 256-thread block
    int eblk2 = (n_edges2 + 63) / 64;

    transform1_k<<<nblk4, 256>>>(emb, Wsrc1, bsrc1, Wdst1, bdst1, n_nodes);
    edge_kernel_coop<<<eblk1, 256>>>(src1, dst1, attn1, n_edges1);
    transform2_fused_k<<<nblk4, 256>>>(Wsrc2, bsrc2, Wdst2, bdst2, n_nodes);
    edge_kernel_coop<<<eblk2, 256>>>(src2, dst2, attn2, n_edges2);
    finalize2_k<<<nblk, 256>>>(out, n_nodes);
}